// round 4
// baseline (speedup 1.0000x reference)
#include <cuda_runtime.h>
#include <cstdint>
#include <cstddef>

typedef unsigned long long ull;

#define NB 8192
#define NT 2048
#define NH 51

// ---------------- shared memory layout (bytes) ----------------
// 3 weight matrices, each stored as Wif [26][52] float4 then Wgo [26][52] float4
//   float4 at (kk, j) = { w_gA(2kk), w_gA(2kk+1), w_gB(2kk), w_gB(2kk+1) }
#define MATF   10816            // floats per matrix (2*26*52*4)
#define MATB   43264            // bytes per matrix
#define O_W    0
#define O_H1   129792           // 8 groups * [2][26][8] ull  (26624 B)
#define O_H2   156416           // same                        (26624 B)
#define O_BS1  183040           // [4][64] float (1024 B)
#define O_BS2  184064           // [4][64] float (1024 B)
#define O_WL   185088           // 52 floats = 26 f32x2 pairs (208 B)
#define SMEM_TOTAL 185344

__device__ __forceinline__ ull ffma2(ull a, ull b, ull c){
    ull d;
    asm("fma.rn.f32x2 %0, %1, %2, %3;" : "=l"(d) : "l"(a), "l"(b), "l"(c));
    return d;
}
__device__ __forceinline__ float lo2(ull a){ return __uint_as_float((unsigned)a); }
__device__ __forceinline__ float hi2(ull a){ return __uint_as_float((unsigned)(a >> 32)); }

__device__ __forceinline__ float fast_sig(float x){
    float e = __expf(-x);             // MUFU.EX2 based
    float r;
    asm("rcp.approx.f32 %0, %1;" : "=f"(r) : "f"(1.0f + e));
    return r;
}
__device__ __forceinline__ float fast_tanh(float x){
    return fmaf(2.0f, fast_sig(x + x), -1.0f);
}
__device__ __forceinline__ void gbar(int id){
    asm volatile("bar.sync %0, %1;" :: "r"(id), "r"(64) : "memory");
}

// stage one [4H, H] matrix into packed Wif/Wgo shared layout
__device__ __forceinline__ void stage_mat(const float* __restrict__ S, float* D, int tid){
    for (int idx = tid; idx < MATF; idx += 512){
        int half = idx / 5408;          // 0 -> gates (i,f), 1 -> gates (g,o)
        int rem  = idx - half*5408;
        int kk   = rem / 208;
        int r    = rem - kk*208;
        int j    = r >> 2;
        int q    = r & 3;
        int gate = half*2 + (q >> 1);
        int k    = 2*kk + (q & 1);
        float v = 0.0f;
        if (j < NH && k < NH) v = S[(gate*NH + j)*NH + k];
        D[idx] = v;
    }
}

__global__ void __launch_bounds__(512, 1)
lstm_kernel(const float* __restrict__ input,
            const float* __restrict__ Wih1, const float* __restrict__ Whh1,
            const float* __restrict__ bih1, const float* __restrict__ bhh1,
            const float* __restrict__ Wih2, const float* __restrict__ Whh2,
            const float* __restrict__ bih2, const float* __restrict__ bhh2,
            const float* __restrict__ Wlin, const float* __restrict__ blin,
            float* __restrict__ out)
{
    extern __shared__ char smem[];
    const int tid = threadIdx.x;

    // ---------------- stage weights / biases, zero h buffers ----------------
    stage_mat(Whh1, (float*)(smem + 0*MATB), tid);
    stage_mat(Wih2, (float*)(smem + 1*MATB), tid);
    stage_mat(Whh2, (float*)(smem + 2*MATB), tid);
    {
        float* bs1 = (float*)(smem + O_BS1);
        float* bs2 = (float*)(smem + O_BS2);
        for (int idx = tid; idx < 256; idx += 512){
            int g = idx >> 6, j = idx & 63;
            float v1 = 0.f, v2 = 0.f;
            if (j < NH){
                v1 = bih1[g*NH + j] + bhh1[g*NH + j];
                v2 = bih2[g*NH + j] + bhh2[g*NH + j];
            }
            bs1[idx] = v1; bs2[idx] = v2;
        }
        float* wl = (float*)(smem + O_WL);
        for (int idx = tid; idx < 52; idx += 512) wl[idx] = (idx < NH) ? Wlin[idx] : 0.f;
        ull* hz = (ull*)(smem + O_H1);
        for (int idx = tid; idx < 6656; idx += 512) hz[idx] = 0ull;  // h1 + h2 buffers
    }
    __syncthreads();

    const int grp = tid >> 6;          // 8 groups of 64 threads
    const int u   = tid & 63;          // hidden unit (active if < 51)
    const int b0  = blockIdx.x * 64 + grp * 8;   // first batch element of this group
    const int bid = grp + 1;           // named barrier id

    typedef ull HBuf[26][8];
    HBuf* h1b = (HBuf*)(smem + O_H1 + grp*3328);   // [2][26][8] pairs {h_2k, h_2k+1} per elem
    HBuf* h2b = (HBuf*)(smem + O_H2 + grp*3328);

    const ulonglong2* Wif1  = (const ulonglong2*)(smem + 0*MATB);
    const ulonglong2* Wgo1  = (const ulonglong2*)(smem + 0*MATB + 21632);
    const ulonglong2* Wif2i = (const ulonglong2*)(smem + 1*MATB);
    const ulonglong2* Wgo2i = (const ulonglong2*)(smem + 1*MATB + 21632);
    const ulonglong2* Wif2h = (const ulonglong2*)(smem + 2*MATB);
    const ulonglong2* Wgo2h = (const ulonglong2*)(smem + 2*MATB + 21632);
    const float* bs1 = (const float*)(smem + O_BS1);
    const float* bs2 = (const float*)(smem + O_BS2);
    const ull*   wlp = (const ull*)(smem + O_WL);

    float wx0 = 0.f, wx1 = 0.f, wx2 = 0.f, wx3 = 0.f;
    if (u < NH){
        wx0 = Wih1[0*NH + u]; wx1 = Wih1[1*NH + u];
        wx2 = Wih1[2*NH + u]; wx3 = Wih1[3*NH + u];
    }
    const float blin0 = blin[0];

    float c1[8], c2[8];
    #pragma unroll
    for (int e = 0; e < 8; e++){ c1[e] = 0.f; c2[e] = 0.f; }

    #pragma unroll 1
    for (int t = 0; t < NT; t++){
        const int cur = t & 1, nxt = cur ^ 1;

        if (u < NH){
            float x[8];
            #pragma unroll
            for (int e = 0; e < 8; e++)
                x[e] = input[(size_t)(b0 + e)*NT + t];

            // ---------------- layer 1 recurrent matvec ----------------
            ull a0[8], a1[8], a2[8], a3[8];
            #pragma unroll
            for (int e = 0; e < 8; e++){ a0[e]=0ull; a1[e]=0ull; a2[e]=0ull; a3[e]=0ull; }

            #pragma unroll 1
            for (int kk = 0; kk < 26; kk++){
                ulonglong2 wif = Wif1[kk*52 + u];
                ulonglong2 wgo = Wgo1[kk*52 + u];
                const ull* hr = h1b[cur][kk];
                #pragma unroll
                for (int p = 0; p < 4; p++){
                    ulonglong2 hp = *(const ulonglong2*)(hr + 2*p);
                    a0[2*p]   = ffma2(hp.x, wif.x, a0[2*p]);
                    a1[2*p]   = ffma2(hp.x, wif.y, a1[2*p]);
                    a2[2*p]   = ffma2(hp.x, wgo.x, a2[2*p]);
                    a3[2*p]   = ffma2(hp.x, wgo.y, a3[2*p]);
                    a0[2*p+1] = ffma2(hp.y, wif.x, a0[2*p+1]);
                    a1[2*p+1] = ffma2(hp.y, wif.y, a1[2*p+1]);
                    a2[2*p+1] = ffma2(hp.y, wgo.x, a2[2*p+1]);
                    a3[2*p+1] = ffma2(hp.y, wgo.y, a3[2*p+1]);
                }
            }
            {
                float bi = bs1[0*64+u], bf = bs1[1*64+u], bg = bs1[2*64+u], bo = bs1[3*64+u];
                float* hw = (float*)&h1b[nxt][u >> 1][0];
                const int hofs = (u & 1);
                #pragma unroll
                for (int e = 0; e < 8; e++){
                    float gi = lo2(a0[e]) + hi2(a0[e]) + fmaf(x[e], wx0, bi);
                    float gf = lo2(a1[e]) + hi2(a1[e]) + fmaf(x[e], wx1, bf);
                    float gg = lo2(a2[e]) + hi2(a2[e]) + fmaf(x[e], wx2, bg);
                    float go = lo2(a3[e]) + hi2(a3[e]) + fmaf(x[e], wx3, bo);
                    float cn = fast_sig(gf)*c1[e] + fast_sig(gi)*fast_tanh(gg);
                    c1[e] = cn;
                    hw[2*e + hofs] = fast_sig(go)*fast_tanh(cn);
                }
            }
        }
        gbar(bid);   // h1(new) visible to whole group

        if (u < NH){
            // ---------------- layer 2: W_ih2 * h1(new) + W_hh2 * h2(old) ----------------
            ull a0[8], a1[8], a2[8], a3[8];
            #pragma unroll
            for (int e = 0; e < 8; e++){ a0[e]=0ull; a1[e]=0ull; a2[e]=0ull; a3[e]=0ull; }

            #pragma unroll 1
            for (int kk = 0; kk < 26; kk++){
                ulonglong2 wia = Wif2i[kk*52 + u];
                ulonglong2 wga = Wgo2i[kk*52 + u];
                ulonglong2 wib = Wif2h[kk*52 + u];
                ulonglong2 wgb = Wgo2h[kk*52 + u];
                const ull* h1r = h1b[nxt][kk];
                const ull* h2r = h2b[cur][kk];
                #pragma unroll
                for (int p = 0; p < 4; p++){
                    ulonglong2 hp = *(const ulonglong2*)(h1r + 2*p);
                    ulonglong2 qp = *(const ulonglong2*)(h2r + 2*p);
                    a0[2*p]   = ffma2(hp.x, wia.x, a0[2*p]);
                    a1[2*p]   = ffma2(hp.x, wia.y, a1[2*p]);
                    a2[2*p]   = ffma2(hp.x, wga.x, a2[2*p]);
                    a3[2*p]   = ffma2(hp.x, wga.y, a3[2*p]);
                    a0[2*p]   = ffma2(qp.x, wib.x, a0[2*p]);
                    a1[2*p]   = ffma2(qp.x, wib.y, a1[2*p]);
                    a2[2*p]   = ffma2(qp.x, wgb.x, a2[2*p]);
                    a3[2*p]   = ffma2(qp.x, wgb.y, a3[2*p]);
                    a0[2*p+1] = ffma2(hp.y, wia.x, a0[2*p+1]);
                    a1[2*p+1] = ffma2(hp.y, wia.y, a1[2*p+1]);
                    a2[2*p+1] = ffma2(hp.y, wga.x, a2[2*p+1]);
                    a3[2*p+1] = ffma2(hp.y, wga.y, a3[2*p+1]);
                    a0[2*p+1] = ffma2(qp.y, wib.x, a0[2*p+1]);
                    a1[2*p+1] = ffma2(qp.y, wib.y, a1[2*p+1]);
                    a2[2*p+1] = ffma2(qp.y, wgb.x, a2[2*p+1]);
                    a3[2*p+1] = ffma2(qp.y, wgb.y, a3[2*p+1]);
                }
            }
            {
                float bi = bs2[0*64+u], bf = bs2[1*64+u], bg = bs2[2*64+u], bo = bs2[3*64+u];
                float* hw = (float*)&h2b[nxt][u >> 1][0];
                const int hofs = (u & 1);
                #pragma unroll
                for (int e = 0; e < 8; e++){
                    float gi = lo2(a0[e]) + hi2(a0[e]) + bi;
                    float gf = lo2(a1[e]) + hi2(a1[e]) + bf;
                    float gg = lo2(a2[e]) + hi2(a2[e]) + bg;
                    float go = lo2(a3[e]) + hi2(a3[e]) + bo;
                    float cn = fast_sig(gf)*c2[e] + fast_sig(gi)*fast_tanh(gg);
                    c2[e] = cn;
                    hw[2*e + hofs] = fast_sig(go)*fast_tanh(cn);
                }
            }
        }
        gbar(bid);   // h2(new) visible

        // ---------------- output projection: one thread per element ----------------
        if (u < 8){
            ull p = 0ull;
            #pragma unroll 1
            for (int kk = 0; kk < 26; kk++)
                p = ffma2(h2b[nxt][kk][u], wlp[kk], p);
            out[(size_t)(b0 + u)*NT + t] = lo2(p) + hi2(p) + blin0;
        }
    }
}

extern "C" void kernel_launch(void* const* d_in, const int* in_sizes, int n_in,
                              void* d_out, int out_size)
{
    (void)in_sizes; (void)n_in; (void)out_size;
    const float* input = (const float*)d_in[0];
    const float* Wih1  = (const float*)d_in[1];
    const float* Whh1  = (const float*)d_in[2];
    const float* bih1  = (const float*)d_in[3];
    const float* bhh1  = (const float*)d_in[4];
    const float* Wih2  = (const float*)d_in[5];
    const float* Whh2  = (const float*)d_in[6];
    const float* bih2  = (const float*)d_in[7];
    const float* bhh2  = (const float*)d_in[8];
    const float* Wlin  = (const float*)d_in[9];
    const float* blin  = (const float*)d_in[10];
    float* out = (float*)d_out;

    cudaFuncSetAttribute(lstm_kernel, cudaFuncAttributeMaxDynamicSharedMemorySize, SMEM_TOTAL);
    lstm_kernel<<<128, 512, SMEM_TOTAL>>>(input, Wih1, Whh1, bih1, bhh1,
                                          Wih2, Whh2, bih2, bhh2, Wlin, blin, out);
}

// round 6
// speedup vs baseline: 2.3172x; 2.3172x over previous
#include <cuda_runtime.h>
#include <cuda_fp16.h>
#include <cstdint>
#include <cstddef>

#define NT 2048

// ---- smem layout (bytes); all A/B rows are 144B (72 halves) ----
#define A1H 0
#define A1L 9216
#define A2H 18432
#define A2L 27648
#define B1H 36864
#define B1L 66816
#define B2AH 96768
#define B2AL 126720
#define B2BH 156672
#define B2BL 186624
#define O_WL 216576
#define O_PART 216784
#define SMEM_TOTAL 217856
#define RST 144

__device__ __forceinline__ uint32_t s2u(const void* p){
    uint32_t a;
    asm("{ .reg .u64 t; cvta.to.shared.u64 t, %1; cvt.u32.u64 %0, t; }" : "=r"(a) : "l"(p));
    return a;
}
__device__ __forceinline__ void ldsm4(uint32_t* r, uint32_t a){
    asm volatile("ldmatrix.sync.aligned.m8n8.x4.shared.b16 {%0,%1,%2,%3}, [%4];"
        : "=r"(r[0]),"=r"(r[1]),"=r"(r[2]),"=r"(r[3]) : "r"(a));
}
__device__ __forceinline__ void ldsm2(uint32_t* r, uint32_t a){
    asm volatile("ldmatrix.sync.aligned.m8n8.x2.shared.b16 {%0,%1}, [%2];"
        : "=r"(r[0]),"=r"(r[1]) : "r"(a));
}
__device__ __forceinline__ void mma16816(float* c, const uint32_t* a, uint32_t b0, uint32_t b1){
    asm volatile("mma.sync.aligned.m16n8k16.row.col.f32.f16.f16.f32 "
        "{%0,%1,%2,%3}, {%4,%5,%6,%7}, {%8,%9}, {%0,%1,%2,%3};"
        : "+f"(c[0]),"+f"(c[1]),"+f"(c[2]),"+f"(c[3])
        : "r"(a[0]),"r"(a[1]),"r"(a[2]),"r"(a[3]), "r"(b0),"r"(b1));
}
__device__ __forceinline__ float fast_sig(float x){
    float e = __expf(-x);
    float r;
    asm("rcp.approx.f32 %0, %1;" : "=f"(r) : "f"(1.0f + e));
    return r;
}
__device__ __forceinline__ float fast_tanh(float x){
    return fmaf(2.0f, fast_sig(x + x), -1.0f);
}
// gate exchange + LSTM cell update; p = tig&1 (0 -> row g, 1 -> row g+8)
__device__ __forceinline__ float epi_update(const float* gc, float& c, int p){
    float r0 = __shfl_xor_sync(0xFFFFFFFFu, gc[0], 1);
    float r1 = __shfl_xor_sync(0xFFFFFFFFu, gc[1], 1);
    float r2 = __shfl_xor_sync(0xFFFFFFFFu, gc[2], 1);
    float r3 = __shfl_xor_sync(0xFFFFFFFFu, gc[3], 1);
    float gi = p ? r2 : gc[0];
    float gf = p ? r3 : gc[1];
    float gG = p ? gc[2] : r0;
    float gO = p ? gc[3] : r1;
    float cn = fast_sig(gf)*c + fast_sig(gi)*fast_tanh(gG);
    c = cn;
    return fast_sig(gO)*fast_tanh(cn);
}
__device__ __forceinline__ void store_h(half* hp, half* lp, int er, int u, float h){
    half hh = __float2half(h);
    half ll = __float2half((h - __half2float(hh)) * 2048.0f);
    hp[er*72 + u] = hh;
    lp[er*72 + u] = ll;
}
// stage [204-row] weight block into [208][72] fp16 hi/lo tile; cols: [0,51)=W, 51=wx, 52=bias
__device__ void stageB(const float* W, const float* wx, const float* ba, const float* bb,
                       half* hi, half* lo, int tid){
    for (int i = tid; i < 208*72; i += 512){
        int n = i / 72, k = i - n*72;
        float v = 0.0f;
        if (n < 204){
            int u = n >> 2, g = n & 3, row = g*51 + u;
            if (k < 51)                 v = W[row*51 + k];
            else if (k == 51 && wx)     v = wx[row];
            else if (k == 52 && ba)     v = ba[row] + bb[row];
        }
        half h = __float2half(v);
        hi[i] = h;
        lo[i] = __float2half((v - __half2float(h)) * 2048.0f);
    }
}

__global__ void __launch_bounds__(512, 1)
lstm_mma_kernel(const float* __restrict__ input,
                const float* __restrict__ Wih1, const float* __restrict__ Whh1,
                const float* __restrict__ bih1, const float* __restrict__ bhh1,
                const float* __restrict__ Wih2, const float* __restrict__ Whh2,
                const float* __restrict__ bih2, const float* __restrict__ bhh2,
                const float* __restrict__ Wlin, const float* __restrict__ blin,
                float* __restrict__ out)
{
    extern __shared__ char smem[];
    const int tid  = threadIdx.x;
    const int lane = tid & 31;
    const int wid  = tid >> 5;
    const int b0   = blockIdx.x * 64;
    const uint32_t sb = s2u(smem);

    half* a1h = (half*)(smem + A1H); half* a1l = (half*)(smem + A1L);
    half* a2h = (half*)(smem + A2H); half* a2l = (half*)(smem + A2L);

    // ---- stage weights + zero A tiles ----
    stageB(Whh1, Wih1, bih1, bhh1, (half*)(smem + B1H),  (half*)(smem + B1L),  tid);
    stageB(Wih2, 0,    bih2, bhh2, (half*)(smem + B2AH), (half*)(smem + B2AL), tid);
    stageB(Whh2, 0,    0,    0,    (half*)(smem + B2BH), (half*)(smem + B2BL), tid);
    for (int i = tid; i < 36864/4; i += 512) ((uint32_t*)(smem + A1H))[i] = 0u;
    if (tid < 52) ((float*)(smem + O_WL))[tid] = (tid < 51) ? Wlin[tid] : 0.0f;
    __syncthreads();
    if (tid < 64){   // x(0) at col 51, ones at col 52
        float xv = input[(size_t)(b0 + tid)*NT];
        store_h(a1h, a1l, tid, 51, xv);
        a1h[tid*72 + 52] = __float2half(1.0f);
    }
    __syncthreads();

    // ---- per-warp geometry ----
    const int mt = wid >> 2;             // m-tile 0..3
    const int q  = wid & 3;              // n-quarter
    const int ns = (q < 2) ? q*7 : 14 + (q - 2)*6;
    const int nt = (q < 2) ? 7 : 6;
    const int m0 = mt * 16;
    const int g   = lane >> 2;
    const int tig = lane & 3;
    const int p   = tig & 1;
    const int er  = m0 + p*8 + g;        // this thread's batch elem (within block)

    // lane-relative ldsm address offsets
    const uint32_t aro = (uint32_t)(((lane>>3)&1)*8*RST + (lane&7)*RST + ((lane>>4)&1)*16);
    const uint32_t bro = (uint32_t)((lane&7)*RST + ((lane>>3)&1)*16);
    const uint32_t a1hb = sb + A1H + m0*RST + aro, a1lb = sb + A1L + m0*RST + aro;
    const uint32_t a2hb = sb + A2H + m0*RST + aro, a2lb = sb + A2L + m0*RST + aro;
    const uint32_t b1hb = sb + B1H + bro, b1lb = sb + B1L + bro;
    const uint32_t bahb = sb + B2AH + bro, balb = sb + B2AL + bro;
    const uint32_t bbhb = sb + B2BH + bro, bblb = sb + B2BL + bro;
    float* part = (float*)(smem + O_PART);
    const float* wlS = (const float*)(smem + O_WL);
    const float blin0 = blin[0];

    float c1[7], c2[7], wlr[7];
    #pragma unroll
    for (int j = 0; j < 7; j++){
        c1[j] = 0.0f; c2[j] = 0.0f;
        int u = 2*(ns + j) + (tig >> 1);
        wlr[j] = (j < nt) ? wlS[u] : 0.0f;
    }

    uint32_t fa1h[16], fa1l[16];
    #pragma unroll
    for (int kc = 0; kc < 4; kc++){      // prime A1 frags (h1=0, x(0), ones)
        ldsm4(&fa1h[kc*4], a1hb + kc*32);
        ldsm4(&fa1l[kc*4], a1lb + kc*32);
    }

    #pragma unroll 1
    for (int t = 0; t < NT; t++){
        float xv = 0.0f;
        if (tid < 64 && t + 1 < NT) xv = input[(size_t)(b0 + tid)*NT + t + 1];

        // ======== phase B: GEMM1 (gates1 = A1 x B1) + epi1 ========
        #pragma unroll
        for (int j = 0; j < 7; j++){
            if (j >= nt) break;
            const uint32_t nofs = (uint32_t)((ns + j)*8*RST);
            float acc1[4] = {0,0,0,0}, acc2[4] = {0,0,0,0};
            #pragma unroll
            for (int kc = 0; kc < 4; kc++){
                uint32_t bh[2], bl[2];
                ldsm2(bh, b1hb + nofs + kc*32);
                ldsm2(bl, b1lb + nofs + kc*32);
                mma16816(acc1, &fa1h[kc*4], bh[0], bh[1]);
                mma16816(acc2, &fa1h[kc*4], bl[0], bl[1]);
                mma16816(acc2, &fa1l[kc*4], bh[0], bh[1]);
            }
            float gc[4];
            #pragma unroll
            for (int r = 0; r < 4; r++) gc[r] = fmaf(acc2[r], 4.8828125e-4f, acc1[r]);
            float h = epi_update(gc, c1[j], p);
            int u = 2*(ns + j) + (tig >> 1);
            if (u < 51) store_h(a1h, a1l, er, u, h);
        }
        if (tid < 64 && t + 1 < NT) store_h(a1h, a1l, tid, 51, xv);
        __syncthreads();   // bar1: h1(t), x(t+1) visible

        // ======== phase C: reload A frags; GEMM2 + epi2 ========
        uint32_t fa2h[16], fa2l[16];
        #pragma unroll
        for (int kc = 0; kc < 4; kc++){
            ldsm4(&fa1h[kc*4], a1hb + kc*32);   // h1(t), x(t+1), ones
            ldsm4(&fa1l[kc*4], a1lb + kc*32);
            ldsm4(&fa2h[kc*4], a2hb + kc*32);   // h2(t-1)
            ldsm4(&fa2l[kc*4], a2lb + kc*32);
        }
        float pd = 0.0f;
        #pragma unroll
        for (int j = 0; j < 7; j++){
            if (j >= nt) break;
            const uint32_t nofs = (uint32_t)((ns + j)*8*RST);
            float acc1[4] = {0,0,0,0}, acc2[4] = {0,0,0,0};
            #pragma unroll
            for (int kc = 0; kc < 4; kc++){
                uint32_t bh[2], bl[2];
                ldsm2(bh, bahb + nofs + kc*32);
                ldsm2(bl, balb + nofs + kc*32);
                mma16816(acc1, &fa1h[kc*4], bh[0], bh[1]);
                mma16816(acc2, &fa1h[kc*4], bl[0], bl[1]);
                mma16816(acc2, &fa1l[kc*4], bh[0], bh[1]);
            }
            #pragma unroll
            for (int kc = 0; kc < 4; kc++){
                uint32_t bh[2], bl[2];
                ldsm2(bh, bbhb + nofs + kc*32);
                ldsm2(bl, bblb + nofs + kc*32);
                mma16816(acc1, &fa2h[kc*4], bh[0], bh[1]);
                mma16816(acc2, &fa2h[kc*4], bl[0], bl[1]);
                mma16816(acc2, &fa2l[kc*4], bh[0], bh[1]);
            }
            float gc[4];
            #pragma unroll
            for (int r = 0; r < 4; r++) gc[r] = fmaf(acc2[r], 4.8828125e-4f, acc1[r]);
            float h = epi_update(gc, c2[j], p);
            int u = 2*(ns + j) + (tig >> 1);
            if (u < 51) store_h(a2h, a2l, er, u, h);
            pd = fmaf(h, wlr[j], pd);
        }
        pd += __shfl_xor_sync(0xFFFFFFFFu, pd, 2);
        if (tig < 2) part[er*4 + q] = pd;
        __syncthreads();   // bar2: A2(h2(t)), part visible

        if (tid < 64)
            out[(size_t)(b0 + tid)*NT + t] =
                part[4*tid] + part[4*tid+1] + part[4*tid+2] + part[4*tid+3] + blin0;
    }
}

extern "C" void kernel_launch(void* const* d_in, const int* in_sizes, int n_in,
                              void* d_out, int out_size)
{
    (void)in_sizes; (void)n_in; (void)out_size;
    const float* input = (const float*)d_in[0];
    const float* Wih1  = (const float*)d_in[1];
    const float* Whh1  = (const float*)d_in[2];
    const float* bih1  = (const float*)d_in[3];
    const float* bhh1  = (const float*)d_in[4];
    const float* Wih2  = (const float*)d_in[5];
    const float* Whh2  = (const float*)d_in[6];
    const float* bih2  = (const float*)d_in[7];
    const float* bhh2  = (const float*)d_in[8];
    const float* Wlin  = (const float*)d_in[9];
    const float* blin  = (const float*)d_in[10];
    float* out = (float*)d_out;

    cudaFuncSetAttribute(lstm_mma_kernel, cudaFuncAttributeMaxDynamicSharedMemorySize, SMEM_TOTAL);
    lstm_mma_kernel<<<128, 512, SMEM_TOTAL>>>(input, Wih1, Whh1, bih1, bhh1,
                                              Wih2, Whh2, bih2, bhh2, Wlin, blin, out);
}

// round 7
// speedup vs baseline: 2.9033x; 1.2529x over previous
#include <cuda_runtime.h>
#include <cuda_fp16.h>
#include <cstdint>
#include <cstddef>

#define NT 2048

// ---- smem layout (bytes); A/B rows are 144B (72 halves) ----
#define A1H    0
#define A2H    9216
#define B1H    18432
#define B1L    48384
#define B2AH   78336
#define B2AL   108288
#define B2BH   138240
#define B2BL   168192
#define O_WL   198144
#define O_PART 198352
#define SMEM_TOTAL 199424
#define RST 144

__device__ __forceinline__ uint32_t s2u(const void* p){
    uint32_t a;
    asm("{ .reg .u64 t; cvta.to.shared.u64 t, %1; cvt.u32.u64 %0, t; }" : "=r"(a) : "l"(p));
    return a;
}
__device__ __forceinline__ void ldsm4(uint32_t* r, uint32_t a){
    asm volatile("ldmatrix.sync.aligned.m8n8.x4.shared.b16 {%0,%1,%2,%3}, [%4];"
        : "=r"(r[0]),"=r"(r[1]),"=r"(r[2]),"=r"(r[3]) : "r"(a));
}
__device__ __forceinline__ void ldsm2(uint32_t* r, uint32_t a){
    asm volatile("ldmatrix.sync.aligned.m8n8.x2.shared.b16 {%0,%1}, [%2];"
        : "=r"(r[0]),"=r"(r[1]) : "r"(a));
}
__device__ __forceinline__ void mma16816(float* c, const uint32_t* a, uint32_t b0, uint32_t b1){
    asm volatile("mma.sync.aligned.m16n8k16.row.col.f32.f16.f16.f32 "
        "{%0,%1,%2,%3}, {%4,%5,%6,%7}, {%8,%9}, {%0,%1,%2,%3};"
        : "+f"(c[0]),"+f"(c[1]),"+f"(c[2]),"+f"(c[3])
        : "r"(a[0]),"r"(a[1]),"r"(a[2]),"r"(a[3]), "r"(b0),"r"(b1));
}
__device__ __forceinline__ float fast_sig(float x){
    float e = __expf(-x);
    float r;
    asm("rcp.approx.f32 %0, %1;" : "=f"(r) : "f"(1.0f + e));
    return r;
}
__device__ __forceinline__ float fast_tanh(float x){
    return fmaf(2.0f, fast_sig(x + x), -1.0f);
}
// gate exchange + LSTM cell update; p = tig&1 (0 -> row g, 1 -> row g+8)
__device__ __forceinline__ float epi_update(const float* gc, float& c, int p){
    float r0 = __shfl_xor_sync(0xFFFFFFFFu, gc[0], 1);
    float r1 = __shfl_xor_sync(0xFFFFFFFFu, gc[1], 1);
    float r2 = __shfl_xor_sync(0xFFFFFFFFu, gc[2], 1);
    float r3 = __shfl_xor_sync(0xFFFFFFFFu, gc[3], 1);
    float gi = p ? r2 : gc[0];
    float gf = p ? r3 : gc[1];
    float gG = p ? gc[2] : r0;
    float gO = p ? gc[3] : r1;
    float cn = fast_sig(gf)*c + fast_sig(gi)*fast_tanh(gG);
    c = cn;
    return fast_sig(gO)*fast_tanh(cn);
}
// stage [204-row] weight block into [208][72] fp16 hi + raw lo tiles
// cols: [0,51)=W, 51=wx, 52=bias
__device__ void stageB(const float* W, const float* wx, const float* ba, const float* bb,
                       half* hi, half* lo, int tid){
    for (int i = tid; i < 208*72; i += 512){
        int n = i / 72, k = i - n*72;
        float v = 0.0f;
        if (n < 204){
            int u = n >> 2, g = n & 3, row = g*51 + u;
            if (k < 51)                 v = W[row*51 + k];
            else if (k == 51 && wx)     v = wx[row];
            else if (k == 52 && ba)     v = ba[row] + bb[row];
        }
        half h = __float2half(v);
        hi[i] = h;
        lo[i] = __float2half(v - __half2float(h));   // raw residual (may be subnormal)
    }
}

__global__ void __launch_bounds__(512, 1)
lstm_mma_kernel(const float* __restrict__ input,
                const float* __restrict__ Wih1, const float* __restrict__ Whh1,
                const float* __restrict__ bih1, const float* __restrict__ bhh1,
                const float* __restrict__ Wih2, const float* __restrict__ Whh2,
                const float* __restrict__ bih2, const float* __restrict__ bhh2,
                const float* __restrict__ Wlin, const float* __restrict__ blin,
                float* __restrict__ out)
{
    extern __shared__ char smem[];
    const int tid  = threadIdx.x;
    const int lane = tid & 31;
    const int wid  = tid >> 5;
    const int b0   = blockIdx.x * 64;
    const uint32_t sb = s2u(smem);

    half* a1h = (half*)(smem + A1H);
    half* a2h = (half*)(smem + A2H);

    // ---- stage weights + zero A tiles ----
    stageB(Whh1, Wih1, bih1, bhh1, (half*)(smem + B1H),  (half*)(smem + B1L),  tid);
    stageB(Wih2, 0,    bih2, bhh2, (half*)(smem + B2AH), (half*)(smem + B2AL), tid);
    stageB(Whh2, 0,    0,    0,    (half*)(smem + B2BH), (half*)(smem + B2BL), tid);
    for (int i = tid; i < 18432/4; i += 512) ((uint32_t*)(smem + A1H))[i] = 0u;
    if (tid < 52) ((float*)(smem + O_WL))[tid] = (tid < 51) ? Wlin[tid] : 0.0f;
    __syncthreads();
    if (tid < 64){   // x(0) at col 51, ones at col 52
        a1h[tid*72 + 51] = __float2half(input[(size_t)(b0 + tid)*NT]);
        a1h[tid*72 + 52] = __float2half(1.0f);
    }
    __syncthreads();

    // ---- per-warp geometry (identical to verified R6) ----
    const int mt = wid >> 2;             // m-tile 0..3
    const int q  = wid & 3;              // n-quarter
    const int ns = (q < 2) ? q*7 : 14 + (q - 2)*6;
    const int nt = (q < 2) ? 7 : 6;
    const int m0 = mt * 16;
    const int g   = lane >> 2;
    const int tig = lane & 3;
    const int p   = tig & 1;
    const int er  = m0 + p*8 + g;        // this thread's batch elem

    const uint32_t aro = (uint32_t)(((lane>>3)&1)*8*RST + (lane&7)*RST + ((lane>>4)&1)*16);
    const uint32_t bro = (uint32_t)((lane&7)*RST + ((lane>>3)&1)*16);
    const uint32_t a1b = sb + A1H + m0*RST + aro;
    const uint32_t a2b = sb + A2H + m0*RST + aro;
    const uint32_t b1hb = sb + B1H  + bro, b1lb = sb + B1L  + bro;
    const uint32_t bahb = sb + B2AH + bro, balb = sb + B2AL + bro;
    const uint32_t bbhb = sb + B2BH + bro, bblb = sb + B2BL + bro;
    float* part = (float*)(smem + O_PART);
    const float* wlS = (const float*)(smem + O_WL);
    const float blin0 = blin[0];

    float c1[7], c2[7], wlr[7], accP[7][4];
    #pragma unroll
    for (int j = 0; j < 7; j++){
        c1[j] = 0.0f; c2[j] = 0.0f;
        int u = 2*(ns + j) + (tig >> 1);
        wlr[j] = (j < nt) ? wlS[u] : 0.0f;
        #pragma unroll
        for (int r = 0; r < 4; r++) accP[j][r] = 0.0f;
    }

    uint32_t fa1[16], fa2[16];
    #pragma unroll
    for (int kc = 0; kc < 4; kc++){      // prime A frags
        ldsm4(&fa1[kc*4], a1b + kc*32);  // [h1=0, x(0), 1]
        ldsm4(&fa2[kc*4], a2b + kc*32);  // h2 = 0
    }

    #pragma unroll 1
    for (int t = 0; t < NT; t++){
        float xv = 0.0f;
        if (tid < 64 && t + 1 < NT) xv = input[(size_t)(b0 + tid)*NT + t + 1];

        // ======== phase B: GEMM1 (A1 x B1 hi+lo) + accP += A2 x B2b; epi1 ========
        #pragma unroll
        for (int j = 0; j < 7; j++){
            if (j >= nt) break;
            const uint32_t nofs = (uint32_t)((ns + j)*8*RST);
            float g1[4] = {0,0,0,0};
            #pragma unroll
            for (int kc = 0; kc < 4; kc++){
                uint32_t bh[2], bb[2];
                ldsm2(bh, b1hb + nofs + kc*32);
                ldsm2(bb, bbhb + nofs + kc*32);
                mma16816(g1, &fa1[kc*4], bh[0], bh[1]);
                mma16816(accP[j], &fa2[kc*4], bb[0], bb[1]);
            }
            #pragma unroll
            for (int kc = 0; kc < 4; kc++){
                uint32_t bl[2], bb[2];
                ldsm2(bl, b1lb + nofs + kc*32);
                ldsm2(bb, bblb + nofs + kc*32);
                mma16816(g1, &fa1[kc*4], bl[0], bl[1]);
                mma16816(accP[j], &fa2[kc*4], bb[0], bb[1]);
            }
            float h = epi_update(g1, c1[j], p);
            int u = 2*(ns + j) + (tig >> 1);
            if (u < 51) a1h[er*72 + u] = __float2half(h);
        }
        if (tid < 64 && t + 1 < NT) a1h[tid*72 + 51] = __float2half(xv);
        __syncthreads();   // bar1: h1(t), x(t+1) visible
        #pragma unroll
        for (int kc = 0; kc < 4; kc++) ldsm4(&fa1[kc*4], a1b + kc*32);

        // ======== phase C: gates2 = accP + A1(new) x B2a (hi+lo); epi2 + out ========
        float pd = 0.0f;
        #pragma unroll
        for (int j = 0; j < 7; j++){
            if (j >= nt) break;
            const uint32_t nofs = (uint32_t)((ns + j)*8*RST);
            #pragma unroll
            for (int kc = 0; kc < 4; kc++){
                uint32_t ba[2];
                ldsm2(ba, bahb + nofs + kc*32);
                mma16816(accP[j], &fa1[kc*4], ba[0], ba[1]);
            }
            #pragma unroll
            for (int kc = 0; kc < 4; kc++){
                uint32_t ba[2];
                ldsm2(ba, balb + nofs + kc*32);
                mma16816(accP[j], &fa1[kc*4], ba[0], ba[1]);
            }
            float h = epi_update(accP[j], c2[j], p);
            #pragma unroll
            for (int r = 0; r < 4; r++) accP[j][r] = 0.0f;
            int u = 2*(ns + j) + (tig >> 1);
            if (u < 51) a2h[er*72 + u] = __float2half(h);
            pd = fmaf(h, wlr[j], pd);
        }
        pd += __shfl_xor_sync(0xFFFFFFFFu, pd, 2);
        if (tig < 2) part[er*4 + q] = pd;
        __syncthreads();   // bar2: A2(h2(t)), part visible
        #pragma unroll
        for (int kc = 0; kc < 4; kc++) ldsm4(&fa2[kc*4], a2b + kc*32);

        if (tid < 64)
            out[(size_t)(b0 + tid)*NT + t] =
                part[4*tid] + part[4*tid+1] + part[4*tid+2] + part[4*tid+3] + blin0;
    }
}

extern "C" void kernel_launch(void* const* d_in, const int* in_sizes, int n_in,
                              void* d_out, int out_size)
{
    (void)in_sizes; (void)n_in; (void)out_size;
    const float* input = (const float*)d_in[0];
    const float* Wih1  = (const float*)d_in[1];
    const float* Whh1  = (const float*)d_in[2];
    const float* bih1  = (const float*)d_in[3];
    const float* bhh1  = (const float*)d_in[4];
    const float* Wih2  = (const float*)d_in[5];
    const float* Whh2  = (const float*)d_in[6];
    const float* bih2  = (const float*)d_in[7];
    const float* bhh2  = (const float*)d_in[8];
    const float* Wlin  = (const float*)d_in[9];
    const float* blin  = (const float*)d_in[10];
    float* out = (float*)d_out;

    cudaFuncSetAttribute(lstm_mma_kernel, cudaFuncAttributeMaxDynamicSharedMemorySize, SMEM_TOTAL);
    lstm_mma_kernel<<<128, 512, SMEM_TOTAL>>>(input, Wih1, Whh1, bih1, bhh1,
                                              Wih2, Whh2, bih2, bhh2, Wlin, blin, out);
}

// round 8
// speedup vs baseline: 3.2083x; 1.1050x over previous
#include <cuda_runtime.h>
#include <cuda_fp16.h>
#include <cstdint>
#include <cstddef>

#define NT 2048

// ---- smem layout (bytes); A/B rows are 144B (72 halves) ----
#define A1H    0
#define A2H    9216
#define B1H    18432
#define B1L    48384
#define B2AH   78336
#define B2AL   108288
#define B2BH   138240
#define B2BL   168192
#define O_WL   198144
#define O_PART 198352
#define SMEM_TOTAL 200448
#define RST 144

__device__ __forceinline__ uint32_t s2u(const void* p){
    uint32_t a;
    asm("{ .reg .u64 t; cvta.to.shared.u64 t, %1; cvt.u32.u64 %0, t; }" : "=r"(a) : "l"(p));
    return a;
}
__device__ __forceinline__ void ldsm4(uint32_t* r, uint32_t a){
    asm volatile("ldmatrix.sync.aligned.m8n8.x4.shared.b16 {%0,%1,%2,%3}, [%4];"
        : "=r"(r[0]),"=r"(r[1]),"=r"(r[2]),"=r"(r[3]) : "r"(a));
}
__device__ __forceinline__ void mma16816(float* c, const uint32_t* a, uint32_t b0, uint32_t b1){
    asm volatile("mma.sync.aligned.m16n8k16.row.col.f32.f16.f16.f32 "
        "{%0,%1,%2,%3}, {%4,%5,%6,%7}, {%8,%9}, {%0,%1,%2,%3};"
        : "+f"(c[0]),"+f"(c[1]),"+f"(c[2]),"+f"(c[3])
        : "r"(a[0]),"r"(a[1]),"r"(a[2]),"r"(a[3]), "r"(b0),"r"(b1));
}
__device__ __forceinline__ float fast_sig(float x){
    float e = __expf(-x);
    float r;
    asm("rcp.approx.f32 %0, %1;" : "=f"(r) : "f"(1.0f + e));
    return r;
}
__device__ __forceinline__ float fast_tanh(float x){
    return fmaf(2.0f, fast_sig(x + x), -1.0f);
}
// gate exchange + LSTM cell update; p = tig&1
__device__ __forceinline__ float epi_update(const float* gc, float& c, int p){
    float r0 = __shfl_xor_sync(0xFFFFFFFFu, gc[0], 1);
    float r1 = __shfl_xor_sync(0xFFFFFFFFu, gc[1], 1);
    float r2 = __shfl_xor_sync(0xFFFFFFFFu, gc[2], 1);
    float r3 = __shfl_xor_sync(0xFFFFFFFFu, gc[3], 1);
    float gi = p ? r2 : gc[0];
    float gf = p ? r3 : gc[1];
    float gG = p ? gc[2] : r0;
    float gO = p ? gc[3] : r1;
    float cn = fast_sig(gf)*c + fast_sig(gi)*fast_tanh(gG);
    c = cn;
    return fast_sig(gO)*fast_tanh(cn);
}
// stage [204-row] weight block into [208][72] fp16 hi + residual-lo tiles
__device__ void stageB(const float* W, const float* wx, const float* ba, const float* bb,
                       half* hi, half* lo, int tid){
    for (int i = tid; i < 208*72; i += 512){
        int n = i / 72, k = i - n*72;
        float v = 0.0f;
        if (n < 204){
            int u = n >> 2, g = n & 3, row = g*51 + u;
            if (k < 51)                 v = W[row*51 + k];
            else if (k == 51 && wx)     v = wx[row];
            else if (k == 52 && ba)     v = ba[row] + bb[row];
        }
        half h = __float2half(v);
        hi[i] = h;
        lo[i] = __float2half(v - __half2float(h));
    }
}

__global__ void __launch_bounds__(512, 1)
lstm_mma_kernel(const float* __restrict__ input,
                const float* __restrict__ Wih1, const float* __restrict__ Whh1,
                const float* __restrict__ bih1, const float* __restrict__ bhh1,
                const float* __restrict__ Wih2, const float* __restrict__ Whh2,
                const float* __restrict__ bih2, const float* __restrict__ bhh2,
                const float* __restrict__ Wlin, const float* __restrict__ blin,
                float* __restrict__ out)
{
    extern __shared__ char smem[];
    const int tid  = threadIdx.x;
    const int lane = tid & 31;
    const int wid  = tid >> 5;
    const int b0   = blockIdx.x * 64;
    const uint32_t sb = s2u(smem);

    half* a1h = (half*)(smem + A1H);
    half* a2h = (half*)(smem + A2H);

    // ---- stage weights + zero A tiles ----
    stageB(Whh1, Wih1, bih1, bhh1, (half*)(smem + B1H),  (half*)(smem + B1L),  tid);
    stageB(Wih2, 0,    bih2, bhh2, (half*)(smem + B2AH), (half*)(smem + B2AL), tid);
    stageB(Whh2, 0,    0,    0,    (half*)(smem + B2BH), (half*)(smem + B2BL), tid);
    for (int i = tid; i < 18432/4; i += 512) ((uint32_t*)(smem + A1H))[i] = 0u;
    if (tid < 52) ((float*)(smem + O_WL))[tid] = (tid < 51) ? Wlin[tid] : 0.0f;
    __syncthreads();
    if (tid < 64){   // x(0) at col 51, ones at col 52
        a1h[tid*72 + 51] = __float2half(input[(size_t)(b0 + tid)*NT]);
        a1h[tid*72 + 52] = __float2half(1.0f);
    }
    __syncthreads();

    // ---- per-warp geometry: 2 m-groups x 8 n-slices ----
    const int q  = wid >> 1;                     // n-slice 0..7
    const int mg = wid & 1;                      // m-group 0..1 (32 rows each)
    const int ns = (q == 0) ? 0 : 4 + 3*(q - 1); // first n-tile
    const int nt = (q == 0 || q == 7) ? 4 : 3;
    const int m0 = mg * 32;
    const int g   = lane >> 2;
    const int tig = lane & 3;
    const int p   = tig & 1;
    const int er0 = m0 + p*8 + g;                // elem for m-tile 0
    const int er1 = er0 + 16;                    // elem for m-tile 1

    // lane-relative ldsm offsets
    const uint32_t aro  = (uint32_t)(((lane>>3)&1)*8*RST + (lane&7)*RST + ((lane>>4)&1)*16);
    const uint32_t bro4 = (uint32_t)((lane&7)*RST + ((lane>>3)&3)*16);
    const uint32_t a1b0 = sb + A1H + m0*RST + aro,      a1b1 = a1b0 + 16*RST;
    const uint32_t a2b0 = sb + A2H + m0*RST + aro,      a2b1 = a2b0 + 16*RST;
    const uint32_t b1hb = sb + B1H  + bro4, b1lb = sb + B1L  + bro4;
    const uint32_t bahb = sb + B2AH + bro4, balb = sb + B2AL + bro4;
    const uint32_t bbhb = sb + B2BH + bro4, bblb = sb + B2BL + bro4;
    float* part = (float*)(smem + O_PART);
    const float* wlS = (const float*)(smem + O_WL);
    const float blin0 = blin[0];

    float c1[2][4], c2[2][4], wlr[4];
    #pragma unroll
    for (int j = 0; j < 4; j++){
        c1[0][j] = c1[1][j] = 0.0f;
        c2[0][j] = c2[1][j] = 0.0f;
        wlr[j] = wlS[2*(ns + j) + (tig >> 1)];
    }

    uint32_t fa1[2][16], fa2[2][16];
    #pragma unroll
    for (int kc = 0; kc < 4; kc++){              // prime A frags
        ldsm4(&fa1[0][kc*4], a1b0 + kc*32);
        ldsm4(&fa1[1][kc*4], a1b1 + kc*32);
        ldsm4(&fa2[0][kc*4], a2b0 + kc*32);
        ldsm4(&fa2[1][kc*4], a2b1 + kc*32);
    }

    #pragma unroll 1
    for (int t = 0; t < NT; t++){
        float xv = 0.0f;
        if (tid < 64 && t + 1 < NT) xv = input[(size_t)(b0 + tid)*NT + t + 1];

        // ======== phase B: layer-1 gates = A1 x B1(hi + K-concat lo); epi1 ========
        #pragma unroll
        for (int j = 0; j < 4; j++){
            if (j >= nt) break;
            const uint32_t nofs = (uint32_t)((ns + j)*8*RST);
            float g1a[4] = {0,0,0,0}, g1b[4] = {0,0,0,0};
            uint32_t b4[4];
            #pragma unroll
            for (int kc2 = 0; kc2 < 2; kc2++){
                ldsm4(b4, b1hb + nofs + kc2*64);
                mma16816(g1a, &fa1[0][(2*kc2)*4],   b4[0], b4[1]);
                mma16816(g1b, &fa1[1][(2*kc2)*4],   b4[0], b4[1]);
                mma16816(g1a, &fa1[0][(2*kc2+1)*4], b4[2], b4[3]);
                mma16816(g1b, &fa1[1][(2*kc2+1)*4], b4[2], b4[3]);
            }
            #pragma unroll
            for (int kc2 = 0; kc2 < 2; kc2++){
                ldsm4(b4, b1lb + nofs + kc2*64);
                mma16816(g1a, &fa1[0][(2*kc2)*4],   b4[0], b4[1]);
                mma16816(g1b, &fa1[1][(2*kc2)*4],   b4[0], b4[1]);
                mma16816(g1a, &fa1[0][(2*kc2+1)*4], b4[2], b4[3]);
                mma16816(g1b, &fa1[1][(2*kc2+1)*4], b4[2], b4[3]);
            }
            float h0 = epi_update(g1a, c1[0][j], p);
            float h1 = epi_update(g1b, c1[1][j], p);
            int u = 2*(ns + j) + (tig >> 1);
            if (u < 51){
                a1h[er0*72 + u] = __float2half(h0);
                a1h[er1*72 + u] = __float2half(h1);
            }
        }
        if (tid < 64 && t + 1 < NT) a1h[tid*72 + 51] = __float2half(xv);
        __syncthreads();   // bar1: h1(t), x(t+1) visible
        #pragma unroll
        for (int kc = 0; kc < 4; kc++){
            ldsm4(&fa1[0][kc*4], a1b0 + kc*32);
            ldsm4(&fa1[1][kc*4], a1b1 + kc*32);
        }

        // ======== phase C: layer-2 gates = A1(new) x B2a + A2 x B2b; epi2 + out ========
        float pd0 = 0.0f, pd1 = 0.0f;
        #pragma unroll
        for (int j = 0; j < 4; j++){
            if (j >= nt) break;
            const uint32_t nofs = (uint32_t)((ns + j)*8*RST);
            float g2a[4] = {0,0,0,0}, g2b[4] = {0,0,0,0};
            uint32_t b4[4];
            #pragma unroll
            for (int kc2 = 0; kc2 < 2; kc2++){
                ldsm4(b4, bahb + nofs + kc2*64);
                mma16816(g2a, &fa1[0][(2*kc2)*4],   b4[0], b4[1]);
                mma16816(g2b, &fa1[1][(2*kc2)*4],   b4[0], b4[1]);
                mma16816(g2a, &fa1[0][(2*kc2+1)*4], b4[2], b4[3]);
                mma16816(g2b, &fa1[1][(2*kc2+1)*4], b4[2], b4[3]);
            }
            #pragma unroll
            for (int kc2 = 0; kc2 < 2; kc2++){
                ldsm4(b4, bbhb + nofs + kc2*64);
                mma16816(g2a, &fa2[0][(2*kc2)*4],   b4[0], b4[1]);
                mma16816(g2b, &fa2[1][(2*kc2)*4],   b4[0], b4[1]);
                mma16816(g2a, &fa2[0][(2*kc2+1)*4], b4[2], b4[3]);
                mma16816(g2b, &fa2[1][(2*kc2+1)*4], b4[2], b4[3]);
            }
            #pragma unroll
            for (int kc2 = 0; kc2 < 2; kc2++){
                ldsm4(b4, balb + nofs + kc2*64);
                mma16816(g2a, &fa1[0][(2*kc2)*4],   b4[0], b4[1]);
                mma16816(g2b, &fa1[1][(2*kc2)*4],   b4[0], b4[1]);
                mma16816(g2a, &fa1[0][(2*kc2+1)*4], b4[2], b4[3]);
                mma16816(g2b, &fa1[1][(2*kc2+1)*4], b4[2], b4[3]);
            }
            #pragma unroll
            for (int kc2 = 0; kc2 < 2; kc2++){
                ldsm4(b4, bblb + nofs + kc2*64);
                mma16816(g2a, &fa2[0][(2*kc2)*4],   b4[0], b4[1]);
                mma16816(g2b, &fa2[1][(2*kc2)*4],   b4[0], b4[1]);
                mma16816(g2a, &fa2[0][(2*kc2+1)*4], b4[2], b4[3]);
                mma16816(g2b, &fa2[1][(2*kc2+1)*4], b4[2], b4[3]);
            }
            float h0 = epi_update(g2a, c2[0][j], p);
            float h1 = epi_update(g2b, c2[1][j], p);
            int u = 2*(ns + j) + (tig >> 1);
            if (u < 51){
                a2h[er0*72 + u] = __float2half(h0);
                a2h[er1*72 + u] = __float2half(h1);
            }
            pd0 = fmaf(h0, wlr[j], pd0);
            pd1 = fmaf(h1, wlr[j], pd1);
        }
        pd0 += __shfl_xor_sync(0xFFFFFFFFu, pd0, 2);
        pd1 += __shfl_xor_sync(0xFFFFFFFFu, pd1, 2);
        if (tig < 2){
            part[er0*8 + q] = pd0;
            part[er1*8 + q] = pd1;
        }
        __syncthreads();   // bar2: a2h(h2(t)), part visible
        #pragma unroll
        for (int kc = 0; kc < 4; kc++){
            ldsm4(&fa2[0][kc*4], a2b0 + kc*32);
            ldsm4(&fa2[1][kc*4], a2b1 + kc*32);
        }

        if (tid < 64){
            const float* pr = part + tid*8;
            out[(size_t)(b0 + tid)*NT + t] =
                ((pr[0] + pr[1]) + (pr[2] + pr[3])) +
                ((pr[4] + pr[5]) + (pr[6] + pr[7])) + blin0;
        }
    }
}

extern "C" void kernel_launch(void* const* d_in, const int* in_sizes, int n_in,
                              void* d_out, int out_size)
{
    (void)in_sizes; (void)n_in; (void)out_size;
    const float* input = (const float*)d_in[0];
    const float* Wih1  = (const float*)d_in[1];
    const float* Whh1  = (const float*)d_in[2];
    const float* bih1  = (const float*)d_in[3];
    const float* bhh1  = (const float*)d_in[4];
    const float* Wih2  = (const float*)d_in[5];
    const float* Whh2  = (const float*)d_in[6];
    const float* bih2  = (const float*)d_in[7];
    const float* bhh2  = (const float*)d_in[8];
    const float* Wlin  = (const float*)d_in[9];
    const float* blin  = (const float*)d_in[10];
    float* out = (float*)d_out;

    cudaFuncSetAttribute(lstm_mma_kernel, cudaFuncAttributeMaxDynamicSharedMemorySize, SMEM_TOTAL);
    lstm_mma_kernel<<<128, 512, SMEM_TOTAL>>>(input, Wih1, Whh1, bih1, bhh1,
                                              Wih2, Whh2, bih2, bhh2, Wlin, blin, out);
}

// round 9
// speedup vs baseline: 3.4547x; 1.0768x over previous
#include <cuda_runtime.h>
#include <cuda_fp16.h>
#include <cstdint>
#include <cstddef>

#define NT 2048
#define RST 144

// ---- smem layout (bytes) ----
#define BUF0   0          // h1 buffer slot 0: [64][72] half
#define BUF1   9216
#define A2H    18432      // h2 state
#define B1H    27648      // B tiles: 208*144 = 29952 each
#define B1L    57600
#define B2AH   87552
#define B2AL   117504
#define B2BH   147456
#define B2BL   177408
#define O_WL   207360
#define O_PART 207616     // [64][8] float
#define SMEM_TOTAL 209920

__device__ __forceinline__ uint32_t s2u(const void* p){
    uint32_t a;
    asm("{ .reg .u64 t; cvta.to.shared.u64 t, %1; cvt.u32.u64 %0, t; }" : "=r"(a) : "l"(p));
    return a;
}
__device__ __forceinline__ void ldsm4(uint32_t* r, uint32_t a){
    asm volatile("ldmatrix.sync.aligned.m8n8.x4.shared.b16 {%0,%1,%2,%3}, [%4];"
        : "=r"(r[0]),"=r"(r[1]),"=r"(r[2]),"=r"(r[3]) : "r"(a));
}
__device__ __forceinline__ void mma16816(float* c, const uint32_t* a, uint32_t b0, uint32_t b1){
    asm volatile("mma.sync.aligned.m16n8k16.row.col.f32.f16.f16.f32 "
        "{%0,%1,%2,%3}, {%4,%5,%6,%7}, {%8,%9}, {%0,%1,%2,%3};"
        : "+f"(c[0]),"+f"(c[1]),"+f"(c[2]),"+f"(c[3])
        : "r"(a[0]),"r"(a[1]),"r"(a[2]),"r"(a[3]), "r"(b0),"r"(b1));
}
__device__ __forceinline__ void nbar_sync(int id, int cnt){
    asm volatile("bar.sync %0, %1;" :: "r"(id), "r"(cnt) : "memory");
}
__device__ __forceinline__ void nbar_arrive(int id, int cnt){
    asm volatile("bar.arrive %0, %1;" :: "r"(id), "r"(cnt) : "memory");
}
__device__ __forceinline__ float fast_sig(float x){
    float e = __expf(-x);
    float r;
    asm("rcp.approx.f32 %0, %1;" : "=f"(r) : "f"(1.0f + e));
    return r;
}
__device__ __forceinline__ float fast_tanh(float x){
    return fmaf(2.0f, fast_sig(x + x), -1.0f);
}
__device__ __forceinline__ float epi_update(const float* gc, float& c, int p){
    float r0 = __shfl_xor_sync(0xFFFFFFFFu, gc[0], 1);
    float r1 = __shfl_xor_sync(0xFFFFFFFFu, gc[1], 1);
    float r2 = __shfl_xor_sync(0xFFFFFFFFu, gc[2], 1);
    float r3 = __shfl_xor_sync(0xFFFFFFFFu, gc[3], 1);
    float gi = p ? r2 : gc[0];
    float gf = p ? r3 : gc[1];
    float gG = p ? gc[2] : r0;
    float gO = p ? gc[3] : r1;
    float cn = fast_sig(gf)*c + fast_sig(gi)*fast_tanh(gG);
    c = cn;
    return fast_sig(gO)*fast_tanh(cn);
}
// stage [204-row] weight block into [208][72] fp16 hi + residual-lo tiles
__device__ void stageB(const float* W, const float* wx, const float* ba, const float* bb,
                       half* hi, half* lo, int tid){
    for (int i = tid; i < 208*72; i += 512){
        int n = i / 72, k = i - n*72;
        float v = 0.0f;
        if (n < 204){
            int u = n >> 2, g = n & 3, row = g*51 + u;
            if (k < 51)                 v = W[row*51 + k];
            else if (k == 51 && wx)     v = wx[row];
            else if (k == 52 && ba)     v = ba[row] + bb[row];
        }
        half h = __float2half(v);
        hi[i] = h;
        lo[i] = __float2half(v - __half2float(h));
    }
}

__global__ void __launch_bounds__(512, 1)
lstm_ws_kernel(const float* __restrict__ input,
               const float* __restrict__ Wih1, const float* __restrict__ Whh1,
               const float* __restrict__ bih1, const float* __restrict__ bhh1,
               const float* __restrict__ Wih2, const float* __restrict__ Whh2,
               const float* __restrict__ bih2, const float* __restrict__ bhh2,
               const float* __restrict__ Wlin, const float* __restrict__ blin,
               float* __restrict__ out)
{
    extern __shared__ char smem[];
    const int tid  = threadIdx.x;
    const int lane = tid & 31;
    const int wid  = tid >> 5;
    const int b0   = blockIdx.x * 64;
    const uint32_t sb = s2u(smem);

    half* buf[2] = { (half*)(smem + BUF0), (half*)(smem + BUF1) };
    half* a2h = (half*)(smem + A2H);

    // ---- init: stage weights, zero state ----
    stageB(Whh1, Wih1, bih1, bhh1, (half*)(smem + B1H),  (half*)(smem + B1L),  tid);
    stageB(Wih2, 0,    bih2, bhh2, (half*)(smem + B2AH), (half*)(smem + B2AL), tid);
    stageB(Whh2, 0,    0,    0,    (half*)(smem + B2BH), (half*)(smem + B2BL), tid);
    for (int i = tid; i < 27648/4; i += 512) ((uint32_t*)(smem + BUF0))[i] = 0u;
    for (int i = tid; i < 512; i += 512) ((float*)(smem + O_PART))[i] = 0.0f;
    for (int i = tid + 512; i < 512; i += 512) {}
    for (int i = tid; i < 64*8; i += 512) ((float*)(smem + O_PART))[i] = 0.0f;
    if (tid < 52) ((float*)(smem + O_WL))[tid] = (tid < 51) ? Wlin[tid] : 0.0f;
    __syncthreads();
    if (tid < 64){
        buf[0][tid*72 + 51] = __float2half(input[(size_t)(b0 + tid)*NT]);  // x(0)
        buf[0][tid*72 + 52] = __float2half(1.0f);
        buf[1][tid*72 + 52] = __float2half(1.0f);
    }
    __syncthreads();

    const int g   = lane >> 2;
    const int tig = lane & 3;
    const int p   = tig & 1;
    const uint32_t aro  = (uint32_t)(((lane>>3)&1)*8*RST + (lane&7)*RST + ((lane>>4)&1)*16);
    const uint32_t bro4 = (uint32_t)((lane&7)*RST + ((lane>>3)&3)*16);
    const float* wlS = (const float*)(smem + O_WL);
    float* part = (float*)(smem + O_PART);

    if (wid < 6){
        // ================= X group: layer-1 recurrence (producer) =================
        const int mg = wid & 1, qx = wid >> 1;
        const int ns = qx * 9;
        const int nt = (qx == 2) ? 8 : 9;
        const int m0 = mg * 32;
        const int er0 = m0 + p*8 + g, er1 = er0 + 16;
        const uint32_t ab[2][2] = {
            { sb + BUF0 + m0*RST + aro, sb + BUF0 + m0*RST + aro + 16*RST },
            { sb + BUF1 + m0*RST + aro, sb + BUF1 + m0*RST + aro + 16*RST } };
        const uint32_t b1hb = sb + B1H + bro4, b1lb = sb + B1L + bro4;

        float c1[2][9];
        #pragma unroll
        for (int j = 0; j < 9; j++){ c1[0][j] = 0.0f; c1[1][j] = 0.0f; }

        uint32_t fa[2][16];
        #pragma unroll
        for (int kc = 0; kc < 4; kc++){
            ldsm4(&fa[0][kc*4], ab[0][0] + kc*32);
            ldsm4(&fa[1][kc*4], ab[0][1] + kc*32);
        }

        #pragma unroll 1
        for (int t = 0; t < NT; t++){
            const int s = t & 1;
            if (t >= 2) nbar_sync(3 + s, 512);            // wait slot s free
            float xv = 0.0f;
            if (tid < 64 && t + 1 < NT) xv = input[(size_t)(b0 + tid)*NT + t + 1];
            half* bh = buf[s];

            #pragma unroll
            for (int j = 0; j < 9; j++){
                if (j >= nt) break;
                const uint32_t nofs = (uint32_t)((ns + j)*8*RST);
                float g1a[4] = {0,0,0,0}, g1b[4] = {0,0,0,0};
                uint32_t b4[4];
                #pragma unroll
                for (int kc2 = 0; kc2 < 2; kc2++){
                    ldsm4(b4, b1hb + nofs + kc2*64);
                    mma16816(g1a, &fa[0][(2*kc2)*4],   b4[0], b4[1]);
                    mma16816(g1b, &fa[1][(2*kc2)*4],   b4[0], b4[1]);
                    mma16816(g1a, &fa[0][(2*kc2+1)*4], b4[2], b4[3]);
                    mma16816(g1b, &fa[1][(2*kc2+1)*4], b4[2], b4[3]);
                }
                #pragma unroll
                for (int kc2 = 0; kc2 < 2; kc2++){
                    ldsm4(b4, b1lb + nofs + kc2*64);
                    mma16816(g1a, &fa[0][(2*kc2)*4],   b4[0], b4[1]);
                    mma16816(g1b, &fa[1][(2*kc2)*4],   b4[0], b4[1]);
                    mma16816(g1a, &fa[0][(2*kc2+1)*4], b4[2], b4[3]);
                    mma16816(g1b, &fa[1][(2*kc2+1)*4], b4[2], b4[3]);
                }
                float h0 = epi_update(g1a, c1[0][j], p);
                float h1 = epi_update(g1b, c1[1][j], p);
                int u = 2*(ns + j) + (tig >> 1);
                if (u < 51){
                    bh[er0*72 + u] = __float2half(h0);
                    bh[er1*72 + u] = __float2half(h1);
                }
            }
            if (tid < 64 && t + 1 < NT) bh[tid*72 + 51] = __float2half(xv);
            __threadfence_block();
            nbar_sync(6, 192);                            // intra-X: buf[s] complete
            nbar_arrive(1 + s, 512);                      // signal full[s] to Y
            #pragma unroll
            for (int kc = 0; kc < 4; kc++){               // reload h1(t) for t+1
                ldsm4(&fa[0][kc*4], ab[s][0] + kc*32);
                ldsm4(&fa[1][kc*4], ab[s][1] + kc*32);
            }
        }
    } else {
        // ================= Y group: layer-2 + output (consumer) =================
        const int yw = wid - 6;
        const int mg = yw & 1, qy = yw >> 1;
        const int nt = (qy == 0) ? 6 : 5;
        const int ns = (qy == 0) ? 0 : 6 + 5*(qy - 1);
        const int m0 = mg * 32;
        const int er0 = m0 + p*8 + g, er1 = er0 + 16;
        const uint32_t ab[2][2] = {
            { sb + BUF0 + m0*RST + aro, sb + BUF0 + m0*RST + aro + 16*RST },
            { sb + BUF1 + m0*RST + aro, sb + BUF1 + m0*RST + aro + 16*RST } };
        const uint32_t a2b0 = sb + A2H + m0*RST + aro, a2b1 = a2b0 + 16*RST;
        const uint32_t bahb = sb + B2AH + bro4, balb = sb + B2AL + bro4;
        const uint32_t bbhb = sb + B2BH + bro4, bblb = sb + B2BL + bro4;
        const float blin0 = blin[0];

        float c2[2][6], wlr[6];
        #pragma unroll
        for (int j = 0; j < 6; j++){
            c2[0][j] = 0.0f; c2[1][j] = 0.0f;
            wlr[j] = wlS[2*(ns + j) + (tig >> 1)];
        }
        uint32_t fa1[2][16], fa2[2][16];
        #pragma unroll
        for (int kc = 0; kc < 4; kc++){                   // h2(-1) = 0
            ldsm4(&fa2[0][kc*4], a2b0 + kc*32);
            ldsm4(&fa2[1][kc*4], a2b1 + kc*32);
        }

        #pragma unroll 1
        for (int t = 0; t < NT; t++){
            const int s = t & 1;
            nbar_sync(1 + s, 512);                        // wait full[s]: h1(t) ready
            #pragma unroll
            for (int kc = 0; kc < 4; kc++){
                ldsm4(&fa1[0][kc*4], ab[s][0] + kc*32);
                ldsm4(&fa1[1][kc*4], ab[s][1] + kc*32);
            }
            float pd0 = 0.0f, pd1 = 0.0f;
            #pragma unroll
            for (int j = 0; j < 6; j++){
                if (j >= nt) break;
                const uint32_t nofs = (uint32_t)((ns + j)*8*RST);
                float g2a[4] = {0,0,0,0}, g2b[4] = {0,0,0,0};
                uint32_t b4[4];
                #pragma unroll
                for (int kc2 = 0; kc2 < 2; kc2++){
                    ldsm4(b4, bahb + nofs + kc2*64);
                    mma16816(g2a, &fa1[0][(2*kc2)*4],   b4[0], b4[1]);
                    mma16816(g2b, &fa1[1][(2*kc2)*4],   b4[0], b4[1]);
                    mma16816(g2a, &fa1[0][(2*kc2+1)*4], b4[2], b4[3]);
                    mma16816(g2b, &fa1[1][(2*kc2+1)*4], b4[2], b4[3]);
                }
                #pragma unroll
                for (int kc2 = 0; kc2 < 2; kc2++){
                    ldsm4(b4, bbhb + nofs + kc2*64);
                    mma16816(g2a, &fa2[0][(2*kc2)*4],   b4[0], b4[1]);
                    mma16816(g2b, &fa2[1][(2*kc2)*4],   b4[0], b4[1]);
                    mma16816(g2a, &fa2[0][(2*kc2+1)*4], b4[2], b4[3]);
                    mma16816(g2b, &fa2[1][(2*kc2+1)*4], b4[2], b4[3]);
                }
                #pragma unroll
                for (int kc2 = 0; kc2 < 2; kc2++){
                    ldsm4(b4, balb + nofs + kc2*64);
                    mma16816(g2a, &fa1[0][(2*kc2)*4],   b4[0], b4[1]);
                    mma16816(g2b, &fa1[1][(2*kc2)*4],   b4[0], b4[1]);
                    mma16816(g2a, &fa1[0][(2*kc2+1)*4], b4[2], b4[3]);
                    mma16816(g2b, &fa1[1][(2*kc2+1)*4], b4[2], b4[3]);
                }
                #pragma unroll
                for (int kc2 = 0; kc2 < 2; kc2++){
                    ldsm4(b4, bblb + nofs + kc2*64);
                    mma16816(g2a, &fa2[0][(2*kc2)*4],   b4[0], b4[1]);
                    mma16816(g2b, &fa2[1][(2*kc2)*4],   b4[0], b4[1]);
                    mma16816(g2a, &fa2[0][(2*kc2+1)*4], b4[2], b4[3]);
                    mma16816(g2b, &fa2[1][(2*kc2+1)*4], b4[2], b4[3]);
                }
                float h0 = epi_update(g2a, c2[0][j], p);
                float h1 = epi_update(g2b, c2[1][j], p);
                int u = 2*(ns + j) + (tig >> 1);
                if (u < 51){
                    a2h[er0*72 + u] = __float2half(h0);
                    a2h[er1*72 + u] = __float2half(h1);
                }
                pd0 = fmaf(h0, wlr[j], pd0);
                pd1 = fmaf(h1, wlr[j], pd1);
            }
            pd0 += __shfl_xor_sync(0xFFFFFFFFu, pd0, 2);
            pd1 += __shfl_xor_sync(0xFFFFFFFFu, pd1, 2);
            if (tig < 2){
                part[er0*8 + qy] = pd0;
                part[er1*8 + qy] = pd1;
            }
            __threadfence_block();
            nbar_sync(5, 320);                            // intra-Y: a2h + part done
            if (tid >= 256 && tid < 320){
                const int ot = tid - 256;
                const float* pr = part + ot*8;
                out[(size_t)(b0 + ot)*NT + t] =
                    (pr[0] + pr[1]) + (pr[2] + pr[3]) + pr[4] + blin0;
            }
            #pragma unroll
            for (int kc = 0; kc < 4; kc++){               // reload h2(t) for t+1
                ldsm4(&fa2[0][kc*4], a2b0 + kc*32);
                ldsm4(&fa2[1][kc*4], a2b1 + kc*32);
            }
            nbar_sync(5, 320);                            // guard fa2 loads vs next writes
            if (t < NT - 2) nbar_arrive(3 + s, 512);      // release slot s to X
        }
    }
}

extern "C" void kernel_launch(void* const* d_in, const int* in_sizes, int n_in,
                              void* d_out, int out_size)
{
    (void)in_sizes; (void)n_in; (void)out_size;
    const float* input = (const float*)d_in[0];
    const float* Wih1  = (const float*)d_in[1];
    const float* Whh1  = (const float*)d_in[2];
    const float* bih1  = (const float*)d_in[3];
    const float* bhh1  = (const float*)d_in[4];
    const float* Wih2  = (const float*)d_in[5];
    const float* Whh2  = (const float*)d_in[6];
    const float* bih2  = (const float*)d_in[7];
    const float* bhh2  = (const float*)d_in[8];
    const float* Wlin  = (const float*)d_in[9];
    const float* blin  = (const float*)d_in[10];
    float* out = (float*)d_out;

    cudaFuncSetAttribute(lstm_ws_kernel, cudaFuncAttributeMaxDynamicSharedMemorySize, SMEM_TOTAL);
    lstm_ws_kernel<<<128, 512, SMEM_TOTAL>>>(input, Wih1, Whh1, bih1, bhh1,
                                             Wih2, Whh2, bih2, bhh2, Wlin, blin, out);
}